// round 13
// baseline (speedup 1.0000x reference)
#include <cuda_runtime.h>
#include <cuda.h>
#include <cuda_fp16.h>
#include <math.h>
#include <stdint.h>

// ---------------- problem constants -----------------------------------------
#define LSEQ  4096
#define NFFT  8192
#define NBINS 512
#define BH    6144         // B*H
#define HDIM  768
#define M1    6912         // BH + HDIM (k rows ride along in GEMM1)
#define K1    4096
#define N1    1024         // 512 bins x (re, im)
#define M2    6144
#define K2    1024
#define N2    4096
#define NCLUSTERS 74

// sm_103a feature pass? (tcgen05/TMEM only exist in arch-specific compile)
#if defined(__CUDA_ARCH__) && (__CUDA_ARCH__ >= 1000) && \
    (defined(__CUDA_ARCH_FEAT_SM103_ALL) || defined(__CUDA_ARCH_SPECIFIC__) || \
     defined(__CUDA_ARCH_FAMILY_SPECIFIC__))
#define HAS_TCGEN05 1
#else
#define HAS_TCGEN05 0
#endif

// ---------------- device scratch (no allocs allowed) ------------------------
// tc mode: g_Wf/g_Wi/g_Z stored TILED (16KB SW128 [128x64] tiles, row-block
// major then k-block). g_A used by the fallback path only (linear).
__device__ __align__(16) __half g_A [(size_t)M1 * K1];
__device__ __align__(16) __half g_Wf[(size_t)N1 * K1];
__device__ __align__(16) __half g_X [(size_t)M1 * N1];   // spectra (LINEAR always)
__device__ __align__(16) __half g_Z [(size_t)M2 * K2];
__device__ __align__(16) __half g_Wi[(size_t)N2 * K2];

// ---------------- generic PTX helpers ----------------------------------------
__device__ __forceinline__ uint32_t smem_u32(const void* p) {
    return (uint32_t)__cvta_generic_to_shared(p);
}
__device__ __forceinline__ void cp16(uint32_t dst, const void* src) {
    asm volatile("cp.async.cg.shared.global [%0], [%1], 16;\n" :: "r"(dst), "l"(src));
}
__device__ __forceinline__ void cp_commit() {
    asm volatile("cp.async.commit_group;\n" ::: "memory");
}
template <int N>
__device__ __forceinline__ void cp_wait() {
    asm volatile("cp.async.wait_group %0;\n" :: "n"(N) : "memory");
}
__device__ __forceinline__ uint32_t cluster_rank() {
    uint32_t r; asm("mov.u32 %0, %%cluster_ctarank;" : "=r"(r)); return r;
}
#define SWZ(off) ((off) ^ (((off) >> 3) & 0x70))

#define MBARRIER_INIT(mbar, count) \
    asm volatile("mbarrier.init.shared.b64 [%0], %1;" :: "r"((uint32_t)(mbar)), "r"((uint32_t)(count)) : "memory")
#define MBARRIER_ARRIVE_LEADER(mbar) \
    asm volatile("{\n\t.reg .b32 la;\n\t" \
        "and.b32 la, %0, 0xFEFFFFFF;\n\t" \
        "mbarrier.arrive.shared::cluster.b64 _, [la];\n\t}" \
        :: "r"((uint32_t)(mbar)) : "memory")
#define MBARRIER_EXPECT_TX(mbar, bytes) \
    asm volatile("mbarrier.arrive.expect_tx.shared.b64 _, [%0], %1;" \
                 :: "r"((uint32_t)(mbar)), "r"((uint32_t)(bytes)) : "memory")
#define MBARRIER_WAIT_PARITY(mbar, parity) do {                                   \
    uint32_t _m = (uint32_t)(mbar); uint32_t _p = (uint32_t)(parity); uint32_t _d; \
    asm volatile("{\n\t.reg .pred p;\n\t"                                         \
        "mbarrier.try_wait.parity.acquire.cta.shared::cta.b64 p, [%1], %2;\n\t"   \
        "selp.b32 %0, 1, 0, p;\n\t}"                                              \
        : "=r"(_d) : "r"(_m), "r"(_p) : "memory");                                \
    if (!_d) {                                                                    \
        asm volatile("{\n\t.reg .pred P1;\n\t"                                    \
            "WL_%=:\n\t"                                                          \
            "mbarrier.try_wait.parity.acquire.cta.shared::cta.b64 P1, [%0], %1, 0x989680;\n\t" \
            "@P1 bra.uni WD_%=;\n\t"                                              \
            "bra.uni WL_%=;\n\t"                                                  \
            "WD_%=:\n\t}" :: "r"(_m), "r"(_p) : "memory");                        \
    } } while (0)
#define CLUSTER_SYNC() do { \
    asm volatile("barrier.cluster.arrive.aligned;" ::: "memory"); \
    asm volatile("barrier.cluster.wait.aligned;" ::: "memory"); } while (0)

// ---------------- setup kernels ----------------------------------------------
#define TWO_PI_OVER_N 7.6699039e-4f   // 2*pi/8192

// fallback only: A = [x;k] fp16 linear
__global__ void convert_inputs(const float2* __restrict__ x2, const float2* __restrict__ k2) {
    size_t i = (size_t)blockIdx.x * 256 + threadIdx.x;
    const size_t XN2 = (size_t)BH * LSEQ / 2;
    float2 v = (i < XN2) ? x2[i] : k2[i - XN2];
    ((__half2*)g_A)[i] = __floats2half2_rn(v.x, v.y);
}

// fill Wf (tc: tiled, fallback: linear)
__global__ void fill_wf(int tiled) {
    int idx = blockIdx.x * 256 + threadIdx.x;   // N1*K1/8 threads
    int n = idx >> 9, c8 = idx & 511;
    int c = c8 << 3;
    int f = n >> 1, odd = n & 1;
    __half h[8];
#pragma unroll
    for (int j = 0; j < 8; j++) {
        int m = (f * (c + j)) & (NFFT - 1);
        float sv, cv;
        __sincosf((float)m * TWO_PI_OVER_N, &sv, &cv);
        h[j] = __float2half_rn(odd ? -sv : cv);
    }
    if (tiled) {
        size_t toff = (((size_t)(n >> 7) * (K1 / 64) + (c8 >> 3)) << 14)
                    + SWZ((n & 127) * 128 + (c8 & 7) * 16);
        *(uint4*)((char*)g_Wf + toff) = *(uint4*)h;
    } else {
        *(uint4*)(g_Wf + (size_t)n * K1 + c) = *(uint4*)h;
    }
}

// Fused middle kernel: pointwise Z (reads linear g_X) + fill Wi
#define PW_BLOCKS 3072
__global__ void mid_pointwise_fillwi(int tiled) {
    if (blockIdx.x < PW_BLOCKS) {
        int idx = blockIdx.x * 256 + threadIdx.x;      // BH*NBINS/4 threads
        int r = idx >> 7, c8 = idx & 127;
        int f4 = c8 << 2;
        int h = r % HDIM;
        uint4 xu = *(const uint4*)(g_X + (size_t)r * N1 + 2 * f4);
        uint4 ku = *(const uint4*)(g_X + (size_t)(BH + h) * N1 + 2 * f4);
        const __half2* xh = (const __half2*)&xu;
        const __half2* kh = (const __half2*)&ku;
        uint4 zu;
        __half2* zh = (__half2*)&zu;
#pragma unroll
        for (int j = 0; j < 4; j++) {
            float2 X = __half22float2(xh[j]);
            float2 K = __half22float2(kh[j]);
            float alpha = ((f4 + j) == 0) ? (1.0f / 8192.0f) : (2.0f / 8192.0f);
            float Zr = alpha * (X.x * K.x - X.y * K.y);
            float Zi = alpha * (X.x * K.y + X.y * K.x);
            zh[j] = __floats2half2_rn(Zr, -Zi);
        }
        if (tiled) {
            size_t toff = (((size_t)(r >> 7) * (K2 / 64) + (c8 >> 3)) << 14)
                        + SWZ((r & 127) * 128 + (c8 & 7) * 16);
            *(uint4*)((char*)g_Z + toff) = zu;
        } else {
            *(uint4*)(g_Z + (size_t)r * K2 + 2 * f4) = zu;
        }
    } else {
        int idx = (blockIdx.x - PW_BLOCKS) * 256 + threadIdx.x;  // N2*K2/8 threads
        int n = idx >> 7, c8 = idx & 127;
        int c = c8 << 3;
        __half h[8];
#pragma unroll
        for (int j = 0; j < 4; j++) {
            int f = (c >> 1) + j;
            int m = (f * n) & (NFFT - 1);
            float sv, cv;
            __sincosf((float)m * TWO_PI_OVER_N, &sv, &cv);
            h[2 * j]     = __float2half_rn(cv);
            h[2 * j + 1] = __float2half_rn(sv);
        }
        if (tiled) {
            size_t toff = (((size_t)(n >> 7) * (K2 / 64) + (c8 >> 3)) << 14)
                        + SWZ((n & 127) * 128 + (c8 & 7) * 16);
            *(uint4*)((char*)g_Wi + toff) = *(uint4*)h;
        } else {
            *(uint4*)(g_Wi + (size_t)n * K2 + c) = *(uint4*)h;
        }
    }
}

// ============ persistent 2-CTA-cluster tcgen05, DUAL-RAIL producers ==========
// 74 persistent clusters. Tile: M=256 (128 rows/CTA), N=512, BK=64, 4-stage.
// B (32KB/stage/CTA): async rail — one bulk copy of two adjacent tiled blocks?
//   (kept as two 16KB bulk copies from tiled g_Wf/g_Wi; tx on own full)
// A (16KB/stage/CTA): SIMT rail — warps 4-6 LDG->(cvt)->STS, then arrive.
// Leader full count = 3 own A-warps + 3 remote A-warps + 1 own B expect
//                     + 1 odd-B forwarder = 8.  Odd full count = 1 (B expect).
constexpr int STG = 4, BK = 64;
constexpr int BLK16K = 16384;
constexpr int STAGE_B = 3 * BLK16K;                    // A + Bg0 + Bg1 = 48 KB
constexpr int SMEM_DYN = 2048 + STG * STAGE_B;

#if HAS_TCGEN05
static constexpr uint64_t SMEM_DESC_BASE_SW128 =
    (uint64_t(2) << 61) | (uint64_t(1) << 46) | (uint64_t(64) << 32) | (uint64_t(1) << 16);
#define MAKE_SMEM_DESC(addr) (SMEM_DESC_BASE_SW128 | ((uint64_t)((addr) >> 4) & 0x3FFF))

#define TCGEN05_ALLOC_CG2(smem_addr, ncols) \
    asm volatile("tcgen05.alloc.cta_group::2.sync.aligned.shared::cta.b32 [%0], %1;" \
                 :: "r"((uint32_t)(smem_addr)), "r"((uint32_t)(ncols)) : "memory")
#define TCGEN05_DEALLOC_CG2(tmem, ncols) \
    asm volatile("tcgen05.dealloc.cta_group::2.sync.aligned.b32 %0, %1;" :: "r"(tmem), "r"((uint32_t)(ncols)))
#define TCGEN05_RELINQ_CG2() \
    asm volatile("tcgen05.relinquish_alloc_permit.cta_group::2.sync.aligned;")
#define TCGEN05_COMMIT_MC_CG2(mbar, mask) \
    asm volatile("tcgen05.commit.cta_group::2.mbarrier::arrive::one.shared::cluster.multicast::cluster.b64 [%0], %1;" \
                 :: "r"((uint32_t)(mbar)), "h"((uint16_t)(mask)) : "memory")
#define TCGEN05_FENCE_AFTER() asm volatile("tcgen05.fence::after_thread_sync;" ::: "memory")
#define TCGEN05_WAIT_LD()     asm volatile("tcgen05.wait::ld.sync.aligned;" ::: "memory")
#define TCGEN05_LD_X32(r, addr) \
    asm volatile("tcgen05.ld.sync.aligned.32x32b.x32.b32 "                         \
        "{%0, %1, %2, %3, %4, %5, %6, %7, %8, %9, %10, %11, %12, %13, %14, %15, "  \
        " %16, %17, %18, %19, %20, %21, %22, %23, %24, %25, %26, %27, %28, %29, %30, %31}, [%32];" \
        : "=r"((r)[0]),  "=r"((r)[1]),  "=r"((r)[2]),  "=r"((r)[3]),               \
          "=r"((r)[4]),  "=r"((r)[5]),  "=r"((r)[6]),  "=r"((r)[7]),               \
          "=r"((r)[8]),  "=r"((r)[9]),  "=r"((r)[10]), "=r"((r)[11]),              \
          "=r"((r)[12]), "=r"((r)[13]), "=r"((r)[14]), "=r"((r)[15]),              \
          "=r"((r)[16]), "=r"((r)[17]), "=r"((r)[18]), "=r"((r)[19]),              \
          "=r"((r)[20]), "=r"((r)[21]), "=r"((r)[22]), "=r"((r)[23]),              \
          "=r"((r)[24]), "=r"((r)[25]), "=r"((r)[26]), "=r"((r)[27]),              \
          "=r"((r)[28]), "=r"((r)[29]), "=r"((r)[30]), "=r"((r)[31])               \
        : "r"(addr))

#define BULK_G2S(dst, src, bytes, mbar) \
    asm volatile("cp.async.bulk.shared::cluster.global.mbarrier::complete_tx::bytes " \
        "[%0], [%1], %2, [%3];" \
        :: "r"((uint32_t)(dst)), "l"(src), "r"((uint32_t)(bytes)), "r"((uint32_t)(mbar)) \
        : "memory")

__device__ __forceinline__ void mma_f16_ss_cg2(uint32_t d, uint64_t ad, uint64_t bd,
                                               uint32_t idesc, uint32_t enable) {
    asm volatile(
        "{\n\t.reg .pred p;\n\t"
        "setp.ne.u32 p, %4, 0;\n\t"
        "tcgen05.mma.cta_group::2.kind::f16 [%0], %1, %2, %3, "
        "{%5, %5, %5, %5, %5, %5, %5, %5}, p;\n\t}"
        :: "r"(d), "l"(ad), "l"(bd), "r"(idesc), "r"(enable), "r"(0u)
        : "memory");
}
#endif // HAS_TCGEN05

// WHICH=1: A = x/k fp32 via SIMT convert; B = g_Wf tiled bulk; C = g_X fp16.
// WHICH=2: A = g_Z tiled via SIMT copy;   B = g_Wi tiled bulk; C = outp fp32.
template <int KK, int WHICH>
__global__ void __launch_bounds__(256, 1) __cluster_dims__(2, 1, 1)
gemm_dual(const float* __restrict__ xin, const float* __restrict__ kin, float* __restrict__ outp) {
#if HAS_TCGEN05
    extern __shared__ char smem[];
    constexpr int NN = (WHICH == 1) ? N1 : N2;
    constexpr int MM = (WHICH == 1) ? M1 : M2;
    constexpr int KT = KK / BK;
    constexpr int MT = MM / 256;
    constexpr int NTn = NN / 512;
    constexpr int NTILES = MT * NTn;
    const char* __restrict__ Btl = (const char*)((WHICH == 1) ? g_Wf : g_Wi);
    const char* __restrict__ Atl = (const char*)g_Z;   // WHICH==2 only

    const uint32_t sb = (smem_u32(smem) + 1023u) & ~1023u;
    const uint32_t mb_full  = sb + 8;
    const uint32_t mb_empty = sb + 40;
    const uint32_t mb_done  = sb + 72;
    const uint32_t mb_free  = sb + 80;
    const uint32_t tb = sb + 1024;

    const int tid = threadIdx.x, wid = tid >> 5, lane = tid & 31;
    const uint32_t rank = cluster_rank();
    const int cid = blockIdx.x >> 1;

    if (tid == 0) {
        for (int s = 0; s < STG; s++) {
            MBARRIER_INIT(mb_full + 8 * s, (rank == 0) ? 8 : 1);
            MBARRIER_INIT(mb_empty + 8 * s, 1);
        }
        MBARRIER_INIT(mb_done, 1);
        MBARRIER_INIT(mb_free, 2);
    }
    if (wid == 4) { TCGEN05_ALLOC_CG2(sb, 512); TCGEN05_RELINQ_CG2(); }
    __syncthreads();
    uint32_t tmem;
    asm volatile("ld.shared.b32 %0, [%1];" : "=r"(tmem) : "r"(sb));
    CLUSTER_SYNC();

    if (wid >= 4 && wid < 7) {
        // -------- dual-rail producers (warps 4-6; w6 lane0 also issues B) -----
        const int ptid = tid - 128;                 // 0..95
        int gs = 0;
        for (int t = cid; t < NTILES; t += NCLUSTERS) {
            const int mt = t % MT, nt = t / MT;
            const int mbase = mt * 256 + (int)rank * 128;
            const float* asrc32 = nullptr;
            const char* asrc16 = nullptr;
            if (WHICH == 1)
                asrc32 = (mbase < BH) ? xin + (size_t)mbase * K1
                                      : kin + (size_t)(mbase - BH) * K1;
            else
                asrc16 = Atl + (((size_t)(mt * 2 + (int)rank) * KT) << 14);
            const size_t bblk0 = (size_t)(nt * 4 + (int)rank) * KT;
            const size_t bblk1 = (size_t)(nt * 4 + 2 + (int)rank) * KT;

            for (int kt = 0; kt < KT; kt++, gs++) {
                const int s = gs & (STG - 1);
                MBARRIER_WAIT_PARITY(mb_empty + 8 * s, ((gs >> 2) + 1) & 1);
                const uint32_t sA = tb + s * STAGE_B;
                if (tid == 192) {                   // B: async rail (own tx)
                    MBARRIER_EXPECT_TX(mb_full + 8 * s, 32768u);
                    BULK_G2S(sA + BLK16K,     Btl + ((bblk0 + kt) << 14), BLK16K, mb_full + 8 * s);
                    BULK_G2S(sA + 2 * BLK16K, Btl + ((bblk1 + kt) << 14), BLK16K, mb_full + 8 * s);
                }
                // A: SIMT rail, 1024 16B chunks over 96 threads
                if (WHICH == 1) {
                    const int k0 = kt * BK;
#pragma unroll
                    for (int i = 0; i < 11; i++) {
                        int ci = ptid + i * 96;
                        if (ci >= 1024) break;
                        int r = ci >> 3, cc = ci & 7;
                        const float4* p = (const float4*)(asrc32 + (size_t)r * K1 + k0 + cc * 8);
                        float4 v0 = p[0], v1 = p[1];
                        __half2 a0 = __floats2half2_rn(v0.x, v0.y);
                        __half2 a1 = __floats2half2_rn(v0.z, v0.w);
                        __half2 a2 = __floats2half2_rn(v1.x, v1.y);
                        __half2 a3 = __floats2half2_rn(v1.z, v1.w);
                        asm volatile("st.shared.v4.b32 [%0], {%1,%2,%3,%4};"
                            :: "r"(sA + SWZ(r * 128 + cc * 16)),
                               "r"(*(uint32_t*)&a0), "r"(*(uint32_t*)&a1),
                               "r"(*(uint32_t*)&a2), "r"(*(uint32_t*)&a3) : "memory");
                    }
                } else {
                    const char* src = asrc16 + ((size_t)kt << 14);
#pragma unroll
                    for (int i = 0; i < 11; i++) {
                        int ci = ptid + i * 96;
                        if (ci >= 1024) break;
                        uint4 v = *(const uint4*)(src + ci * 16);
                        asm volatile("st.shared.v4.b32 [%0], {%1,%2,%3,%4};"
                            :: "r"(sA + ci * 16), "r"(v.x), "r"(v.y), "r"(v.z), "r"(v.w)
                            : "memory");
                    }
                }
                asm volatile("fence.proxy.async.shared::cta;" ::: "memory");
                if (lane == 0) MBARRIER_ARRIVE_LEADER(mb_full + 8 * s);  // 3/CTA
            }
        }
    } else if (rank == 1 && wid == 7 && lane == 0) {
        // -------- odd-CTA B forwarder (warp 7 lane 0) --------------------------
        int gs = 0;
        for (int t = cid; t < NTILES; t += NCLUSTERS)
            for (int kt = 0; kt < KT; kt++, gs++) {
                const int s = gs & (STG - 1);
                MBARRIER_WAIT_PARITY(mb_full + 8 * s, (gs >> 2) & 1);
                MBARRIER_ARRIVE_LEADER(mb_full + 8 * s);
            }
    } else if (rank == 0 && tid == 224) {
        // -------- MMA issuer (leader, warp 7 lane 0) ---------------------------
        const uint32_t idesc = (1u << 4) | (32u << 17) | (16u << 24);  // F32, N=256, M=256
        int gs = 0, it = 0;
        for (int t = cid; t < NTILES; t += NCLUSTERS, it++) {
            MBARRIER_WAIT_PARITY(mb_free, (it + 1) & 1);
            for (int kt = 0; kt < KT; kt++, gs++) {
                const int s = gs & (STG - 1);
                MBARRIER_WAIT_PARITY(mb_full + 8 * s, (gs >> 2) & 1);
                const uint64_t ad = MAKE_SMEM_DESC(tb + s * STAGE_B);
                const uint64_t bd = MAKE_SMEM_DESC(tb + s * STAGE_B + BLK16K);
#pragma unroll
                for (int j = 0; j < 4; j++) {
                    uint32_t en = (uint32_t)((kt | j) != 0);
                    mma_f16_ss_cg2(tmem,       ad + 2 * j, bd + 2 * j,        idesc, en);
                    mma_f16_ss_cg2(tmem + 256, ad + 2 * j, bd + 1024 + 2 * j, idesc, en);
                }
                TCGEN05_COMMIT_MC_CG2(mb_empty + 8 * s, 3);
            }
            TCGEN05_COMMIT_MC_CG2(mb_done, 3);
        }
    } else if (tid < 128) {
        // -------- epilogue (warps 0-3, every CTA) ------------------------------
        int it = 0;
        for (int t = cid; t < NTILES; t += NCLUSTERS, it++) {
            MBARRIER_WAIT_PARITY(mb_done, it & 1);
            TCGEN05_FENCE_AFTER();
            const int mt = t % MT, nt = t / MT;
            const int grow = mt * 256 + (int)rank * 128 + wid * 32 + lane;
#pragma unroll
            for (int c0 = 0; c0 < 512; c0 += 32) {
                uint32_t r[32];
                TCGEN05_LD_X32(r, tmem + c0);
                TCGEN05_WAIT_LD();
                if (WHICH == 1) {
                    uint4 u[2], v[2];
                    __half2* hp = (__half2*)u;
                    __half2* vp = (__half2*)v;
#pragma unroll
                    for (int q = 0; q < 8; q++) {
                        hp[q] = __floats2half2_rn(__uint_as_float(r[2 * q]), __uint_as_float(r[2 * q + 1]));
                        vp[q] = __floats2half2_rn(__uint_as_float(r[16 + 2 * q]), __uint_as_float(r[17 + 2 * q]));
                    }
                    __half* dst = g_X + (size_t)grow * NN + nt * 512 + c0;
                    *(uint4*)(dst)      = u[0];
                    *(uint4*)(dst + 8)  = u[1];
                    *(uint4*)(dst + 16) = v[0];
                    *(uint4*)(dst + 24) = v[1];
                } else {
                    float* dst = outp + (size_t)grow * NN + nt * 512 + c0;
#pragma unroll
                    for (int q = 0; q < 8; q++) {
                        float4 v4 = make_float4(__uint_as_float(r[4 * q + 0]), __uint_as_float(r[4 * q + 1]),
                                                __uint_as_float(r[4 * q + 2]), __uint_as_float(r[4 * q + 3]));
                        *(float4*)(dst + 4 * q) = v4;
                    }
                }
            }
            asm volatile("bar.sync 1, 128;" ::: "memory");
            if (tid == 0) MBARRIER_ARRIVE_LEADER(mb_free);
        }
    }

    __syncthreads();
    if (wid == 4) TCGEN05_DEALLOC_CG2(tmem, 512);
    CLUSTER_SYNC();
#endif // HAS_TCGEN05
}

// ================= HMMA fallback (compiles everywhere; linear layouts) ========
__device__ __forceinline__ void ldsm4(uint32_t& r0, uint32_t& r1, uint32_t& r2, uint32_t& r3, uint32_t a) {
    asm volatile("ldmatrix.sync.aligned.m8n8.x4.shared.b16 {%0,%1,%2,%3}, [%4];\n"
                 : "=r"(r0), "=r"(r1), "=r"(r2), "=r"(r3) : "r"(a));
}
__device__ __forceinline__ void mma16816(float* c, uint32_t a0, uint32_t a1, uint32_t a2, uint32_t a3,
                                         uint32_t b0, uint32_t b1) {
    asm volatile(
        "mma.sync.aligned.m16n8k16.row.col.f32.f16.f16.f32 "
        "{%0,%1,%2,%3}, {%4,%5,%6,%7}, {%8,%9}, {%0,%1,%2,%3};\n"
        : "+f"(c[0]), "+f"(c[1]), "+f"(c[2]), "+f"(c[3])
        : "r"(a0), "r"(a1), "r"(a2), "r"(a3), "r"(b0), "r"(b1));
}

template <int MM, int NN, int KK, int WHICH>
__global__ void __launch_bounds__(256, 2) gemm_hmma(float* __restrict__ outp) {
    const __half* __restrict__ A = (WHICH == 1) ? g_A  : g_Z;
    const __half* __restrict__ B = (WHICH == 1) ? g_Wf : g_Wi;

    constexpr int FBM = 128, FBN = 128, FBK = 32;
    constexpr int LDT = FBK + 8;
    __shared__ __align__(16) __half As[2][FBM * LDT];
    __shared__ __align__(16) __half Bs[2][FBN * LDT];

    const int tid = threadIdx.x, lane = tid & 31, wid = tid >> 5;
    const int wm = wid & 3, wn = wid >> 2;
    const int bm = blockIdx.y * FBM, bn = blockIdx.x * FBN;

    float acc[2][8][4];
#pragma unroll
    for (int i = 0; i < 2; i++)
#pragma unroll
        for (int j = 0; j < 8; j++)
#pragma unroll
            for (int q = 0; q < 4; q++) acc[i][j][q] = 0.f;

    const int trow = tid >> 2, tcol = (tid & 3) << 3;
    auto load_tile = [&](int kt, int buf) {
        const int k0 = kt * FBK;
        const __half* ag = A + (size_t)(bm + trow) * KK + k0 + tcol;
        cp16(smem_u32(&As[buf][trow * LDT + tcol]), ag);
        cp16(smem_u32(&As[buf][(trow + 64) * LDT + tcol]), ag + (size_t)64 * KK);
        const __half* bg = B + (size_t)(bn + trow) * KK + k0 + tcol;
        cp16(smem_u32(&Bs[buf][trow * LDT + tcol]), bg);
        cp16(smem_u32(&Bs[buf][(trow + 64) * LDT + tcol]), bg + (size_t)64 * KK);
        cp_commit();
    };

    load_tile(0, 0);
    constexpr int KT = KK / FBK;
    for (int kt = 0; kt < KT; kt++) {
        const int buf = kt & 1;
        if (kt + 1 < KT) { load_tile(kt + 1, buf ^ 1); cp_wait<1>(); }
        else            { cp_wait<0>(); }
        __syncthreads();
#pragma unroll
        for (int ks = 0; ks < 2; ks++) {
            uint32_t a[2][4], b[4][4];
#pragma unroll
            for (int mt = 0; mt < 2; mt++) {
                int r = wm * 32 + mt * 16 + (lane & 15);
                int c = ks * 16 + ((lane >> 4) << 3);
                ldsm4(a[mt][0], a[mt][1], a[mt][2], a[mt][3], smem_u32(&As[buf][r * LDT + c]));
            }
#pragma unroll
            for (int nt = 0; nt < 4; nt++) {
                int r = wn * 64 + nt * 16 + (lane & 15);
                int c = ks * 16 + ((lane >> 4) << 3);
                ldsm4(b[nt][0], b[nt][1], b[nt][2], b[nt][3], smem_u32(&Bs[buf][r * LDT + c]));
            }
#pragma unroll
            for (int mt = 0; mt < 2; mt++)
#pragma unroll
                for (int nt = 0; nt < 8; nt++)
                    mma16816(acc[mt][nt], a[mt][0], a[mt][1], a[mt][2], a[mt][3],
                             b[nt >> 1][nt & 1], b[nt >> 1][(nt & 1) + 2]);
        }
        __syncthreads();
    }
#pragma unroll
    for (int mt = 0; mt < 2; mt++)
#pragma unroll
        for (int nt = 0; nt < 8; nt++) {
            int row = bm + wm * 32 + mt * 16 + (lane >> 2);
            int col = bn + wn * 64 + nt * 8 + ((lane & 3) << 1);
            if (WHICH == 1) {
                g_X[(size_t)row * NN + col]           = __float2half_rn(acc[mt][nt][0]);
                g_X[(size_t)row * NN + col + 1]       = __float2half_rn(acc[mt][nt][1]);
                g_X[(size_t)(row + 8) * NN + col]     = __float2half_rn(acc[mt][nt][2]);
                g_X[(size_t)(row + 8) * NN + col + 1] = __float2half_rn(acc[mt][nt][3]);
            } else {
                outp[(size_t)row * NN + col]           = acc[mt][nt][0];
                outp[(size_t)row * NN + col + 1]       = acc[mt][nt][1];
                outp[(size_t)(row + 8) * NN + col]     = acc[mt][nt][2];
                outp[(size_t)(row + 8) * NN + col + 1] = acc[mt][nt][3];
            }
        }
}

// ---------------- launch -------------------------------------------------------
extern "C" void kernel_launch(void* const* d_in, const int* in_sizes, int n_in,
                              void* d_out, int out_size) {
    const float* x = (const float*)d_in[0];
    const float* k = (const float*)d_in[1];
    float* out = (float*)d_out;

    cudaFuncAttributes fa{};
    bool use_tc = (cudaFuncGetAttributes(&fa, (const void*)gemm_dual<K1, 1>) == cudaSuccess)
                  && (fa.numRegs >= 40);
    const int tiled = use_tc ? 1 : 0;

    fill_wf<<<(N1 * K1 / 8) / 256, 256>>>(tiled);

    if (use_tc) {
        cudaFuncSetAttribute((const void*)gemm_dual<K1, 1>,
                             cudaFuncAttributeMaxDynamicSharedMemorySize, SMEM_DYN);
        cudaFuncSetAttribute((const void*)gemm_dual<K2, 2>,
                             cudaFuncAttributeMaxDynamicSharedMemorySize, SMEM_DYN);
        gemm_dual<K1, 1><<<dim3(2 * NCLUSTERS, 1), 256, SMEM_DYN>>>(x, k, nullptr);
        mid_pointwise_fillwi<<<PW_BLOCKS + (N2 * K2 / 8) / 256, 256>>>(tiled);
        gemm_dual<K2, 2><<<dim3(2 * NCLUSTERS, 1), 256, SMEM_DYN>>>(x, k, out);
    } else {
        convert_inputs<<<(M1 * K1 / 2) / 256, 256>>>((const float2*)x, (const float2*)k);
        gemm_hmma<M1, N1, K1, 1><<<dim3(N1 / 128, M1 / 128), 256>>>(nullptr);
        mid_pointwise_fillwi<<<PW_BLOCKS + (N2 * K2 / 8) / 256, 256>>>(tiled);
        gemm_hmma<M2, N2, K2, 2><<<dim3(N2 / 128, M2 / 128), 256>>>(out);
    }
}

// round 14
// speedup vs baseline: 1.1665x; 1.1665x over previous
#include <cuda_runtime.h>
#include <cuda.h>
#include <cuda_fp16.h>
#include <math.h>
#include <stdint.h>

// ---------------- problem constants -----------------------------------------
#define LSEQ  4096
#define NFFT  8192
#define NBINS 512
#define BH    6144         // B*H
#define HDIM  768
#define M1    6912         // BH + HDIM (k rows ride along in GEMM1)
#define K1    4096
#define N1    1024         // 512 bins x (re, im)
#define M2    6144
#define K2    1024
#define N2    4096
#define NCLUSTERS 148      // persistent 2-CTA clusters, 2 CTAs per SM

// sm_103a feature pass? (tcgen05/TMEM only exist in arch-specific compile)
#if defined(__CUDA_ARCH__) && (__CUDA_ARCH__ >= 1000) && \
    (defined(__CUDA_ARCH_FEAT_SM103_ALL) || defined(__CUDA_ARCH_SPECIFIC__) || \
     defined(__CUDA_ARCH_FAMILY_SPECIFIC__))
#define HAS_TCGEN05 1
#else
#define HAS_TCGEN05 0
#endif

// ---------------- device scratch (no allocs allowed) ------------------------
// tc mode: g_A/g_Wf/g_Z/g_Wi stored TILED: 16KB SW128 [128 rows x 64 halves]
// tiles, row-block-major then k-block. g_X always linear.
__device__ __align__(16) __half g_A [(size_t)M1 * K1];
__device__ __align__(16) __half g_Wf[(size_t)N1 * K1];
__device__ __align__(16) __half g_X [(size_t)M1 * N1];
__device__ __align__(16) __half g_Z [(size_t)M2 * K2];
__device__ __align__(16) __half g_Wi[(size_t)N2 * K2];

// ---------------- generic PTX helpers ----------------------------------------
__device__ __forceinline__ uint32_t smem_u32(const void* p) {
    return (uint32_t)__cvta_generic_to_shared(p);
}
__device__ __forceinline__ void cp16(uint32_t dst, const void* src) {
    asm volatile("cp.async.cg.shared.global [%0], [%1], 16;\n" :: "r"(dst), "l"(src));
}
__device__ __forceinline__ void cp_commit() {
    asm volatile("cp.async.commit_group;\n" ::: "memory");
}
template <int N>
__device__ __forceinline__ void cp_wait() {
    asm volatile("cp.async.wait_group %0;\n" :: "n"(N) : "memory");
}
__device__ __forceinline__ uint32_t cluster_rank() {
    uint32_t r; asm("mov.u32 %0, %%cluster_ctarank;" : "=r"(r)); return r;
}
#define SWZ(off) ((off) ^ (((off) >> 3) & 0x70))

#define MBARRIER_INIT(mbar, count) \
    asm volatile("mbarrier.init.shared.b64 [%0], %1;" :: "r"((uint32_t)(mbar)), "r"((uint32_t)(count)) : "memory")
#define MBARRIER_ARRIVE_LEADER(mbar) \
    asm volatile("{\n\t.reg .b32 la;\n\t" \
        "and.b32 la, %0, 0xFEFFFFFF;\n\t" \
        "mbarrier.arrive.shared::cluster.b64 _, [la];\n\t}" \
        :: "r"((uint32_t)(mbar)) : "memory")
#define MBARRIER_EXPECT_TX(mbar, bytes) \
    asm volatile("mbarrier.arrive.expect_tx.shared.b64 _, [%0], %1;" \
                 :: "r"((uint32_t)(mbar)), "r"((uint32_t)(bytes)) : "memory")
#define MBARRIER_WAIT_PARITY(mbar, parity) do {                                   \
    uint32_t _m = (uint32_t)(mbar); uint32_t _p = (uint32_t)(parity); uint32_t _d; \
    asm volatile("{\n\t.reg .pred p;\n\t"                                         \
        "mbarrier.try_wait.parity.acquire.cta.shared::cta.b64 p, [%1], %2;\n\t"   \
        "selp.b32 %0, 1, 0, p;\n\t}"                                              \
        : "=r"(_d) : "r"(_m), "r"(_p) : "memory");                                \
    if (!_d) {                                                                    \
        asm volatile("{\n\t.reg .pred P1;\n\t"                                    \
            "WL_%=:\n\t"                                                          \
            "mbarrier.try_wait.parity.acquire.cta.shared::cta.b64 P1, [%0], %1, 0x989680;\n\t" \
            "@P1 bra.uni WD_%=;\n\t"                                              \
            "bra.uni WL_%=;\n\t"                                                  \
            "WD_%=:\n\t}" :: "r"(_m), "r"(_p) : "memory");                        \
    } } while (0)
#define CLUSTER_SYNC() do { \
    asm volatile("barrier.cluster.arrive.aligned;" ::: "memory"); \
    asm volatile("barrier.cluster.wait.aligned;" ::: "memory"); } while (0)

// ---------------- setup kernels ----------------------------------------------
#define TWO_PI_OVER_N 7.6699039e-4f   // 2*pi/8192

// Fused pre kernel: convert inputs to fp16 g_A + fill Wf (tiled in tc mode).
#define CV_BLOCKS 13824   // M1*K1/8/256
__global__ void pre_convert_fillwf(const float* __restrict__ x, const float* __restrict__ k,
                                   int tiled) {
    if (blockIdx.x < CV_BLOCKS) {
        int ci = blockIdx.x * 256 + threadIdx.x;
        int r = ci >> 9, c8 = ci & 511;
        const float* src = (r < BH) ? x + (size_t)r * K1 + c8 * 8
                                    : k + (size_t)(r - BH) * K1 + c8 * 8;
        float4 v0 = ((const float4*)src)[0], v1 = ((const float4*)src)[1];
        uint4 u;
        __half2* hp = (__half2*)&u;
        hp[0] = __floats2half2_rn(v0.x, v0.y);
        hp[1] = __floats2half2_rn(v0.z, v0.w);
        hp[2] = __floats2half2_rn(v1.x, v1.y);
        hp[3] = __floats2half2_rn(v1.z, v1.w);
        if (tiled) {
            size_t toff = (((size_t)(r >> 7) * (K1 / 64) + (c8 >> 3)) << 14)
                        + SWZ((r & 127) * 128 + (c8 & 7) * 16);
            *(uint4*)((char*)g_A + toff) = u;
        } else {
            *(uint4*)(g_A + (size_t)r * K1 + c8 * 8) = u;
        }
    } else {
        int idx = (blockIdx.x - CV_BLOCKS) * 256 + threadIdx.x;
        int n = idx >> 9, c8 = idx & 511;
        int c = c8 << 3;
        int f = n >> 1, odd = n & 1;
        __half h[8];
#pragma unroll
        for (int j = 0; j < 8; j++) {
            int m = (f * (c + j)) & (NFFT - 1);
            float sv, cv;
            __sincosf((float)m * TWO_PI_OVER_N, &sv, &cv);
            h[j] = __float2half_rn(odd ? -sv : cv);
        }
        if (tiled) {
            size_t toff = (((size_t)(n >> 7) * (K1 / 64) + (c8 >> 3)) << 14)
                        + SWZ((n & 127) * 128 + (c8 & 7) * 16);
            *(uint4*)((char*)g_Wf + toff) = *(uint4*)h;
        } else {
            *(uint4*)(g_Wf + (size_t)n * K1 + c) = *(uint4*)h;
        }
    }
}

// Fused middle kernel: pointwise Z (reads linear g_X) + fill Wi
#define PW_BLOCKS 3072
__global__ void mid_pointwise_fillwi(int tiled) {
    if (blockIdx.x < PW_BLOCKS) {
        int idx = blockIdx.x * 256 + threadIdx.x;
        int r = idx >> 7, c8 = idx & 127;
        int f4 = c8 << 2;
        int h = r % HDIM;
        uint4 xu = *(const uint4*)(g_X + (size_t)r * N1 + 2 * f4);
        uint4 ku = *(const uint4*)(g_X + (size_t)(BH + h) * N1 + 2 * f4);
        const __half2* xh = (const __half2*)&xu;
        const __half2* kh = (const __half2*)&ku;
        uint4 zu;
        __half2* zh = (__half2*)&zu;
#pragma unroll
        for (int j = 0; j < 4; j++) {
            float2 X = __half22float2(xh[j]);
            float2 K = __half22float2(kh[j]);
            float alpha = ((f4 + j) == 0) ? (1.0f / 8192.0f) : (2.0f / 8192.0f);
            float Zr = alpha * (X.x * K.x - X.y * K.y);
            float Zi = alpha * (X.x * K.y + X.y * K.x);
            zh[j] = __floats2half2_rn(Zr, -Zi);
        }
        if (tiled) {
            size_t toff = (((size_t)(r >> 7) * (K2 / 64) + (c8 >> 3)) << 14)
                        + SWZ((r & 127) * 128 + (c8 & 7) * 16);
            *(uint4*)((char*)g_Z + toff) = zu;
        } else {
            *(uint4*)(g_Z + (size_t)r * K2 + 2 * f4) = zu;
        }
    } else {
        int idx = (blockIdx.x - PW_BLOCKS) * 256 + threadIdx.x;
        int n = idx >> 7, c8 = idx & 127;
        int c = c8 << 3;
        __half h[8];
#pragma unroll
        for (int j = 0; j < 4; j++) {
            int f = (c >> 1) + j;
            int m = (f * n) & (NFFT - 1);
            float sv, cv;
            __sincosf((float)m * TWO_PI_OVER_N, &sv, &cv);
            h[2 * j]     = __float2half_rn(cv);
            h[2 * j + 1] = __float2half_rn(sv);
        }
        if (tiled) {
            size_t toff = (((size_t)(n >> 7) * (K2 / 64) + (c8 >> 3)) << 14)
                        + SWZ((n & 127) * 128 + (c8 & 7) * 16);
            *(uint4*)((char*)g_Wi + toff) = *(uint4*)h;
        } else {
            *(uint4*)(g_Wi + (size_t)n * K2 + c) = *(uint4*)h;
        }
    }
}

// ======= persistent 2-CTA-cluster tcgen05, TWO CTAS PER SM (small tiles) =====
// 148 persistent clusters = 296 CTAs = 2 co-resident CTAs per SM, each with
// its own async pipeline (tests the per-CTA delivery-rate hypothesis).
// Cluster tile: M=256 (128/CTA) x N=256 (one cg2 MMA). BK=64, 3-stage ring,
// stage = A 16KB + B 16KB = 32KB. SMEM ~98KB/CTA, TMEM 256 cols/CTA.
constexpr int STG = 3, BK = 64;
constexpr int BLK16K = 16384;
constexpr int STAGE_B = 2 * BLK16K;                    // 32 KB
constexpr int SMEM_DYN = 2048 + STG * STAGE_B;         // 100352 B

#if HAS_TCGEN05
static constexpr uint64_t SMEM_DESC_BASE_SW128 =
    (uint64_t(2) << 61) | (uint64_t(1) << 46) | (uint64_t(64) << 32) | (uint64_t(1) << 16);
#define MAKE_SMEM_DESC(addr) (SMEM_DESC_BASE_SW128 | ((uint64_t)((addr) >> 4) & 0x3FFF))

#define TCGEN05_ALLOC_CG2(smem_addr, ncols) \
    asm volatile("tcgen05.alloc.cta_group::2.sync.aligned.shared::cta.b32 [%0], %1;" \
                 :: "r"((uint32_t)(smem_addr)), "r"((uint32_t)(ncols)) : "memory")
#define TCGEN05_DEALLOC_CG2(tmem, ncols) \
    asm volatile("tcgen05.dealloc.cta_group::2.sync.aligned.b32 %0, %1;" :: "r"(tmem), "r"((uint32_t)(ncols)))
#define TCGEN05_RELINQ_CG2() \
    asm volatile("tcgen05.relinquish_alloc_permit.cta_group::2.sync.aligned;")
#define TCGEN05_COMMIT_MC_CG2(mbar, mask) \
    asm volatile("tcgen05.commit.cta_group::2.mbarrier::arrive::one.shared::cluster.multicast::cluster.b64 [%0], %1;" \
                 :: "r"((uint32_t)(mbar)), "h"((uint16_t)(mask)) : "memory")
#define TCGEN05_FENCE_AFTER() asm volatile("tcgen05.fence::after_thread_sync;" ::: "memory")
#define TCGEN05_WAIT_LD()     asm volatile("tcgen05.wait::ld.sync.aligned;" ::: "memory")
#define TCGEN05_LD_X32(r, addr) \
    asm volatile("tcgen05.ld.sync.aligned.32x32b.x32.b32 "                         \
        "{%0, %1, %2, %3, %4, %5, %6, %7, %8, %9, %10, %11, %12, %13, %14, %15, "  \
        " %16, %17, %18, %19, %20, %21, %22, %23, %24, %25, %26, %27, %28, %29, %30, %31}, [%32];" \
        : "=r"((r)[0]),  "=r"((r)[1]),  "=r"((r)[2]),  "=r"((r)[3]),               \
          "=r"((r)[4]),  "=r"((r)[5]),  "=r"((r)[6]),  "=r"((r)[7]),               \
          "=r"((r)[8]),  "=r"((r)[9]),  "=r"((r)[10]), "=r"((r)[11]),              \
          "=r"((r)[12]), "=r"((r)[13]), "=r"((r)[14]), "=r"((r)[15]),              \
          "=r"((r)[16]), "=r"((r)[17]), "=r"((r)[18]), "=r"((r)[19]),              \
          "=r"((r)[20]), "=r"((r)[21]), "=r"((r)[22]), "=r"((r)[23]),              \
          "=r"((r)[24]), "=r"((r)[25]), "=r"((r)[26]), "=r"((r)[27]),              \
          "=r"((r)[28]), "=r"((r)[29]), "=r"((r)[30]), "=r"((r)[31])               \
        : "r"(addr))

#define BULK_G2S(dst, src, bytes, mbar) \
    asm volatile("cp.async.bulk.shared::cluster.global.mbarrier::complete_tx::bytes " \
        "[%0], [%1], %2, [%3];" \
        :: "r"((uint32_t)(dst)), "l"(src), "r"((uint32_t)(bytes)), "r"((uint32_t)(mbar)) \
        : "memory")

__device__ __forceinline__ void mma_f16_ss_cg2(uint32_t d, uint64_t ad, uint64_t bd,
                                               uint32_t idesc, uint32_t enable) {
    asm volatile(
        "{\n\t.reg .pred p;\n\t"
        "setp.ne.u32 p, %4, 0;\n\t"
        "tcgen05.mma.cta_group::2.kind::f16 [%0], %1, %2, %3, "
        "{%5, %5, %5, %5, %5, %5, %5, %5}, p;\n\t}"
        :: "r"(d), "l"(ad), "l"(bd), "r"(idesc), "r"(enable), "r"(0u)
        : "memory");
}
#endif // HAS_TCGEN05

// WHICH=1: A=g_A(tiled), B=g_Wf(tiled), C=g_X fp16 (M1,N1,K1).
// WHICH=2: A=g_Z(tiled), B=g_Wi(tiled), C=outp fp32 (M2,N2,K2).
template <int KK, int WHICH>
__global__ void __launch_bounds__(256, 2) __cluster_dims__(2, 1, 1)
gemm_blk(float* __restrict__ outp) {
#if HAS_TCGEN05
    extern __shared__ char smem[];
    constexpr int NN = (WHICH == 1) ? N1 : N2;
    constexpr int MM = (WHICH == 1) ? M1 : M2;
    constexpr int KT = KK / BK;
    constexpr int MT = MM / 256;
    constexpr int NTn = NN / 256;
    constexpr int NTILES = MT * NTn;
    const char* __restrict__ Atl = (const char*)((WHICH == 1) ? g_A : g_Z);
    const char* __restrict__ Btl = (const char*)((WHICH == 1) ? g_Wf : g_Wi);

    const uint32_t sb = (smem_u32(smem) + 1023u) & ~1023u;
    const uint32_t mb_full  = sb + 8;    // 3 x 8B, per-CTA
    const uint32_t mb_empty = sb + 40;   // 3 x 8B
    const uint32_t mb_done  = sb + 72;
    const uint32_t mb_free  = sb + 80;
    const uint32_t tb = sb + 1024;

    const int tid = threadIdx.x, wid = tid >> 5, lane = tid & 31;
    const uint32_t rank = cluster_rank();
    const int cid = blockIdx.x >> 1;

    if (tid == 0) {
        for (int s = 0; s < STG; s++) {
            MBARRIER_INIT(mb_full + 8 * s, (rank == 0) ? 2 : 1);  // expect(+fwd)
            MBARRIER_INIT(mb_empty + 8 * s, 1);
        }
        MBARRIER_INIT(mb_done, 1);
        MBARRIER_INIT(mb_free, 2);
    }
    if (wid == 4) { TCGEN05_ALLOC_CG2(sb, 256); TCGEN05_RELINQ_CG2(); }
    __syncthreads();
    uint32_t tmem;
    asm volatile("ld.shared.b32 %0, [%1];" : "=r"(tmem) : "r"(sb));
    CLUSTER_SYNC();

    if (tid == 192) {
        // ---------------- bulk producer (warp 6 lane 0, every CTA) ------------
        int s = 0, ph = 0;
        for (int t = cid; t < NTILES; t += NCLUSTERS) {
            const int mt = t % MT, nt = t / MT;
            const size_t ablk = (size_t)(mt * 2 + (int)rank) * KT;
            const size_t bblk = (size_t)(nt * 2 + (int)rank) * KT;
            for (int kt = 0; kt < KT; kt++) {
                MBARRIER_WAIT_PARITY(mb_empty + 8 * s, ph ^ 1);
                MBARRIER_EXPECT_TX(mb_full + 8 * s, 32768u);
                const uint32_t sA = tb + s * STAGE_B;
                BULK_G2S(sA,          Atl + ((ablk + kt) << 14), BLK16K, mb_full + 8 * s);
                BULK_G2S(sA + BLK16K, Btl + ((bblk + kt) << 14), BLK16K, mb_full + 8 * s);
                if (++s == STG) { s = 0; ph ^= 1; }
            }
        }
    } else if (rank == 1 && tid == 160) {
        // ---------------- completion forwarder (odd CTA, warp 5 lane 0) -------
        int s = 0, ph = 0;
        for (int t = cid; t < NTILES; t += NCLUSTERS)
            for (int kt = 0; kt < KT; kt++) {
                MBARRIER_WAIT_PARITY(mb_full + 8 * s, ph);
                MBARRIER_ARRIVE_LEADER(mb_full + 8 * s);
                if (++s == STG) { s = 0; ph ^= 1; }
            }
    } else if (rank == 0 && tid == 224) {
        // ---------------- MMA issuer (leader, warp 7 lane 0) ------------------
        const uint32_t idesc = (1u << 4) | (32u << 17) | (16u << 24);  // F32, N=256, M=256
        int s = 0, ph = 0, it = 0;
        for (int t = cid; t < NTILES; t += NCLUSTERS, it++) {
            MBARRIER_WAIT_PARITY(mb_free, (it + 1) & 1);
            for (int kt = 0; kt < KT; kt++) {
                MBARRIER_WAIT_PARITY(mb_full + 8 * s, ph);
                const uint64_t ad = MAKE_SMEM_DESC(tb + s * STAGE_B);
                const uint64_t bd = MAKE_SMEM_DESC(tb + s * STAGE_B + BLK16K);
#pragma unroll
                for (int j = 0; j < 4; j++)
                    mma_f16_ss_cg2(tmem, ad + 2 * j, bd + 2 * j, idesc,
                                   (uint32_t)((kt | j) != 0));
                TCGEN05_COMMIT_MC_CG2(mb_empty + 8 * s, 3);
                if (++s == STG) { s = 0; ph ^= 1; }
            }
            TCGEN05_COMMIT_MC_CG2(mb_done, 3);
        }
    } else if (tid < 128) {
        // ---------------- epilogue (warps 0-3, every CTA) ---------------------
        int it = 0;
        for (int t = cid; t < NTILES; t += NCLUSTERS, it++) {
            MBARRIER_WAIT_PARITY(mb_done, it & 1);
            TCGEN05_FENCE_AFTER();
            const int mt = t % MT, nt = t / MT;
            const int grow = mt * 256 + (int)rank * 128 + wid * 32 + lane;
#pragma unroll
            for (int c0 = 0; c0 < 256; c0 += 32) {
                uint32_t r[32];
                TCGEN05_LD_X32(r, tmem + c0);
                TCGEN05_WAIT_LD();
                if (WHICH == 1) {
                    uint4 u[2], v[2];
                    __half2* hp = (__half2*)u;
                    __half2* vp = (__half2*)v;
#pragma unroll
                    for (int q = 0; q < 8; q++) {
                        hp[q] = __floats2half2_rn(__uint_as_float(r[2 * q]), __uint_as_float(r[2 * q + 1]));
                        vp[q] = __floats2half2_rn(__uint_as_float(r[16 + 2 * q]), __uint_as_float(r[17 + 2 * q]));
                    }
                    __half* dst = g_X + (size_t)grow * NN + nt * 256 + c0;
                    *(uint4*)(dst)      = u[0];
                    *(uint4*)(dst + 8)  = u[1];
                    *(uint4*)(dst + 16) = v[0];
                    *(uint4*)(dst + 24) = v[1];
                } else {
                    float* dst = outp + (size_t)grow * NN + nt * 256 + c0;
#pragma unroll
                    for (int q = 0; q < 8; q++) {
                        float4 v4 = make_float4(__uint_as_float(r[4 * q + 0]), __uint_as_float(r[4 * q + 1]),
                                                __uint_as_float(r[4 * q + 2]), __uint_as_float(r[4 * q + 3]));
                        *(float4*)(dst + 4 * q) = v4;
                    }
                }
            }
            asm volatile("bar.sync 1, 128;" ::: "memory");
            if (tid == 0) MBARRIER_ARRIVE_LEADER(mb_free);
        }
    }

    __syncthreads();
    if (wid == 4) TCGEN05_DEALLOC_CG2(tmem, 256);
    CLUSTER_SYNC();
#endif // HAS_TCGEN05
}

// ================= HMMA fallback (compiles everywhere; linear layouts) ========
__device__ __forceinline__ void ldsm4(uint32_t& r0, uint32_t& r1, uint32_t& r2, uint32_t& r3, uint32_t a) {
    asm volatile("ldmatrix.sync.aligned.m8n8.x4.shared.b16 {%0,%1,%2,%3}, [%4];\n"
                 : "=r"(r0), "=r"(r1), "=r"(r2), "=r"(r3) : "r"(a));
}
__device__ __forceinline__ void mma16816(float* c, uint32_t a0, uint32_t a1, uint32_t a2, uint32_t a3,
                                         uint32_t b0, uint32_t b1) {
    asm volatile(
        "mma.sync.aligned.m16n8k16.row.col.f32.f16.f16.f32 "
        "{%0,%1,%2,%3}, {%4,%5,%6,%7}, {%8,%9}, {%0,%1,%2,%3};\n"
        : "+f"(c[0]), "+f"(c[1]), "+f"(c[2]), "+f"(c[3])
        : "r"(a0), "r"(a1), "r"(a2), "r"(a3), "r"(b0), "r"(b1));
}

template <int MM, int NN, int KK, int WHICH>
__global__ void __launch_bounds__(256, 2) gemm_hmma(float* __restrict__ outp) {
    const __half* __restrict__ A = (WHICH == 1) ? g_A  : g_Z;
    const __half* __restrict__ B = (WHICH == 1) ? g_Wf : g_Wi;

    constexpr int FBM = 128, FBN = 128, FBK = 32;
    constexpr int LDT = FBK + 8;
    __shared__ __align__(16) __half As[2][FBM * LDT];
    __shared__ __align__(16) __half Bs[2][FBN * LDT];

    const int tid = threadIdx.x, lane = tid & 31, wid = tid >> 5;
    const int wm = wid & 3, wn = wid >> 2;
    const int bm = blockIdx.y * FBM, bn = blockIdx.x * FBN;

    float acc[2][8][4];
#pragma unroll
    for (int i = 0; i < 2; i++)
#pragma unroll
        for (int j = 0; j < 8; j++)
#pragma unroll
            for (int q = 0; q < 4; q++) acc[i][j][q] = 0.f;

    const int trow = tid >> 2, tcol = (tid & 3) << 3;
    auto load_tile = [&](int kt, int buf) {
        const int k0 = kt * FBK;
        const __half* ag = A + (size_t)(bm + trow) * KK + k0 + tcol;
        cp16(smem_u32(&As[buf][trow * LDT + tcol]), ag);
        cp16(smem_u32(&As[buf][(trow + 64) * LDT + tcol]), ag + (size_t)64 * KK);
        const __half* bg = B + (size_t)(bn + trow) * KK + k0 + tcol;
        cp16(smem_u32(&Bs[buf][trow * LDT + tcol]), bg);
        cp16(smem_u32(&Bs[buf][(trow + 64) * LDT + tcol]), bg + (size_t)64 * KK);
        cp_commit();
    };

    load_tile(0, 0);
    constexpr int KT = KK / FBK;
    for (int kt = 0; kt < KT; kt++) {
        const int buf = kt & 1;
        if (kt + 1 < KT) { load_tile(kt + 1, buf ^ 1); cp_wait<1>(); }
        else            { cp_wait<0>(); }
        __syncthreads();
#pragma unroll
        for (int ks = 0; ks < 2; ks++) {
            uint32_t a[2][4], b[4][4];
#pragma unroll
            for (int mt = 0; mt < 2; mt++) {
                int r = wm * 32 + mt * 16 + (lane & 15);
                int c = ks * 16 + ((lane >> 4) << 3);
                ldsm4(a[mt][0], a[mt][1], a[mt][2], a[mt][3], smem_u32(&As[buf][r * LDT + c]));
            }
#pragma unroll
            for (int nt = 0; nt < 4; nt++) {
                int r = wn * 64 + nt * 16 + (lane & 15);
                int c = ks * 16 + ((lane >> 4) << 3);
                ldsm4(b[nt][0], b[nt][1], b[nt][2], b[nt][3], smem_u32(&Bs[buf][r * LDT + c]));
            }
#pragma unroll
            for (int mt = 0; mt < 2; mt++)
#pragma unroll
                for (int nt = 0; nt < 8; nt++)
                    mma16816(acc[mt][nt], a[mt][0], a[mt][1], a[mt][2], a[mt][3],
                             b[nt >> 1][nt & 1], b[nt >> 1][(nt & 1) + 2]);
        }
        __syncthreads();
    }
#pragma unroll
    for (int mt = 0; mt < 2; mt++)
#pragma unroll
        for (int nt = 0; nt < 8; nt++) {
            int row = bm + wm * 32 + mt * 16 + (lane >> 2);
            int col = bn + wn * 64 + nt * 8 + ((lane & 3) << 1);
            if (WHICH == 1) {
                g_X[(size_t)row * NN + col]           = __float2half_rn(acc[mt][nt][0]);
                g_X[(size_t)row * NN + col + 1]       = __float2half_rn(acc[mt][nt][1]);
                g_X[(size_t)(row + 8) * NN + col]     = __float2half_rn(acc[mt][nt][2]);
                g_X[(size_t)(row + 8) * NN + col + 1] = __float2half_rn(acc[mt][nt][3]);
            } else {
                outp[(size_t)row * NN + col]           = acc[mt][nt][0];
                outp[(size_t)row * NN + col + 1]       = acc[mt][nt][1];
                outp[(size_t)(row + 8) * NN + col]     = acc[mt][nt][2];
                outp[(size_t)(row + 8) * NN + col + 1] = acc[mt][nt][3];
            }
        }
}

// ---------------- launch -------------------------------------------------------
extern "C" void kernel_launch(void* const* d_in, const int* in_sizes, int n_in,
                              void* d_out, int out_size) {
    const float* x = (const float*)d_in[0];
    const float* k = (const float*)d_in[1];
    float* out = (float*)d_out;

    cudaFuncAttributes fa{};
    bool use_tc = (cudaFuncGetAttributes(&fa, (const void*)gemm_blk<K1, 1>) == cudaSuccess)
                  && (fa.numRegs >= 40);
    const int tiled = use_tc ? 1 : 0;

    pre_convert_fillwf<<<CV_BLOCKS + (N1 * K1 / 8) / 256, 256>>>(x, k, tiled);

    if (use_tc) {
        cudaFuncSetAttribute((const void*)gemm_blk<K1, 1>,
                             cudaFuncAttributeMaxDynamicSharedMemorySize, SMEM_DYN);
        cudaFuncSetAttribute((const void*)gemm_blk<K2, 2>,
                             cudaFuncAttributeMaxDynamicSharedMemorySize, SMEM_DYN);
        gemm_blk<K1, 1><<<dim3(2 * NCLUSTERS, 1), 256, SMEM_DYN>>>(nullptr);
        mid_pointwise_fillwi<<<PW_BLOCKS + (N2 * K2 / 8) / 256, 256>>>(tiled);
        gemm_blk<K2, 2><<<dim3(2 * NCLUSTERS, 1), 256, SMEM_DYN>>>(out);
    } else {
        gemm_hmma<M1, N1, K1, 1><<<dim3(N1 / 128, M1 / 128), 256>>>(nullptr);
        mid_pointwise_fillwi<<<PW_BLOCKS + (N2 * K2 / 8) / 256, 256>>>(tiled);
        gemm_hmma<M2, N2, K2, 2><<<dim3(N2 / 128, M2 / 128), 256>>>(out);
    }
}

// round 15
// speedup vs baseline: 1.1856x; 1.0164x over previous
#include <cuda_runtime.h>
#include <cuda.h>
#include <cuda_fp16.h>
#include <math.h>
#include <stdint.h>

// ---------------- problem constants -----------------------------------------
#define LSEQ  4096
#define NFFT  8192
#define NBINS 512
#define BH    6144         // B*H
#define HDIM  768
#define M1    6912         // BH + HDIM (k rows ride along in GEMM1)
#define K1    4096
#define N1    1024         // 512 bins x (re, im)
#define M2    6144
#define K2    1024
#define N2    4096
#define NCL   74           // persistent 4-CTA clusters, 2 CTAs per SM

// sm_103a feature pass? (tcgen05/TMEM only exist in arch-specific compile)
#if defined(__CUDA_ARCH__) && (__CUDA_ARCH__ >= 1000) && \
    (defined(__CUDA_ARCH_FEAT_SM103_ALL) || defined(__CUDA_ARCH_SPECIFIC__) || \
     defined(__CUDA_ARCH_FAMILY_SPECIFIC__))
#define HAS_TCGEN05 1
#else
#define HAS_TCGEN05 0
#endif

// ---------------- device scratch (no allocs allowed) ------------------------
// tc mode: g_A/g_Wf/g_Z/g_Wi stored TILED: 16KB SW128 [128 rows x 64 halves]
// tiles, row-block-major then k-block. g_X always linear.
__device__ __align__(16) __half g_A [(size_t)M1 * K1];
__device__ __align__(16) __half g_Wf[(size_t)N1 * K1];
__device__ __align__(16) __half g_X [(size_t)M1 * N1];
__device__ __align__(16) __half g_Z [(size_t)M2 * K2];
__device__ __align__(16) __half g_Wi[(size_t)N2 * K2];

// ---------------- generic PTX helpers ----------------------------------------
__device__ __forceinline__ uint32_t smem_u32(const void* p) {
    return (uint32_t)__cvta_generic_to_shared(p);
}
__device__ __forceinline__ void cp16(uint32_t dst, const void* src) {
    asm volatile("cp.async.cg.shared.global [%0], [%1], 16;\n" :: "r"(dst), "l"(src));
}
__device__ __forceinline__ void cp_commit() {
    asm volatile("cp.async.commit_group;\n" ::: "memory");
}
template <int N>
__device__ __forceinline__ void cp_wait() {
    asm volatile("cp.async.wait_group %0;\n" :: "n"(N) : "memory");
}
__device__ __forceinline__ uint32_t cluster_rank() {
    uint32_t r; asm("mov.u32 %0, %%cluster_ctarank;" : "=r"(r)); return r;
}
#define SWZ(off) ((off) ^ (((off) >> 3) & 0x70))

#define MBARRIER_INIT(mbar, count) \
    asm volatile("mbarrier.init.shared.b64 [%0], %1;" :: "r"((uint32_t)(mbar)), "r"((uint32_t)(count)) : "memory")
#define MBARRIER_ARRIVE_LEADER(mbar) \
    asm volatile("{\n\t.reg .b32 la;\n\t" \
        "and.b32 la, %0, 0xFEFFFFFF;\n\t" \
        "mbarrier.arrive.shared::cluster.b64 _, [la];\n\t}" \
        :: "r"((uint32_t)(mbar)) : "memory")
#define MBARRIER_EXPECT_TX(mbar, bytes) \
    asm volatile("mbarrier.arrive.expect_tx.shared.b64 _, [%0], %1;" \
                 :: "r"((uint32_t)(mbar)), "r"((uint32_t)(bytes)) : "memory")
#define MBARRIER_WAIT_PARITY(mbar, parity) do {                                   \
    uint32_t _m = (uint32_t)(mbar); uint32_t _p = (uint32_t)(parity); uint32_t _d; \
    asm volatile("{\n\t.reg .pred p;\n\t"                                         \
        "mbarrier.try_wait.parity.acquire.cta.shared::cta.b64 p, [%1], %2;\n\t"   \
        "selp.b32 %0, 1, 0, p;\n\t}"                                              \
        : "=r"(_d) : "r"(_m), "r"(_p) : "memory");                                \
    if (!_d) {                                                                    \
        asm volatile("{\n\t.reg .pred P1;\n\t"                                    \
            "WL_%=:\n\t"                                                          \
            "mbarrier.try_wait.parity.acquire.cta.shared::cta.b64 P1, [%0], %1, 0x989680;\n\t" \
            "@P1 bra.uni WD_%=;\n\t"                                              \
            "bra.uni WL_%=;\n\t"                                                  \
            "WD_%=:\n\t}" :: "r"(_m), "r"(_p) : "memory");                        \
    } } while (0)
#define CLUSTER_SYNC() do { \
    asm volatile("barrier.cluster.arrive.aligned;" ::: "memory"); \
    asm volatile("barrier.cluster.wait.aligned;" ::: "memory"); } while (0)

// ---------------- setup kernels ----------------------------------------------
#define TWO_PI_OVER_N 7.6699039e-4f   // 2*pi/8192

// Fused pre kernel: convert inputs to fp16 g_A + fill Wf (tiled in tc mode).
#define CV_BLOCKS 13824   // M1*K1/8/256
__global__ void pre_convert_fillwf(const float* __restrict__ x, const float* __restrict__ k,
                                   int tiled) {
    if (blockIdx.x < CV_BLOCKS) {
        int ci = blockIdx.x * 256 + threadIdx.x;
        int r = ci >> 9, c8 = ci & 511;
        const float* src = (r < BH) ? x + (size_t)r * K1 + c8 * 8
                                    : k + (size_t)(r - BH) * K1 + c8 * 8;
        float4 v0 = ((const float4*)src)[0], v1 = ((const float4*)src)[1];
        uint4 u;
        __half2* hp = (__half2*)&u;
        hp[0] = __floats2half2_rn(v0.x, v0.y);
        hp[1] = __floats2half2_rn(v0.z, v0.w);
        hp[2] = __floats2half2_rn(v1.x, v1.y);
        hp[3] = __floats2half2_rn(v1.z, v1.w);
        if (tiled) {
            size_t toff = (((size_t)(r >> 7) * (K1 / 64) + (c8 >> 3)) << 14)
                        + SWZ((r & 127) * 128 + (c8 & 7) * 16);
            *(uint4*)((char*)g_A + toff) = u;
        } else {
            *(uint4*)(g_A + (size_t)r * K1 + c8 * 8) = u;
        }
    } else {
        int idx = (blockIdx.x - CV_BLOCKS) * 256 + threadIdx.x;
        int n = idx >> 9, c8 = idx & 511;
        int c = c8 << 3;
        int f = n >> 1, odd = n & 1;
        __half h[8];
#pragma unroll
        for (int j = 0; j < 8; j++) {
            int m = (f * (c + j)) & (NFFT - 1);
            float sv, cv;
            __sincosf((float)m * TWO_PI_OVER_N, &sv, &cv);
            h[j] = __float2half_rn(odd ? -sv : cv);
        }
        if (tiled) {
            size_t toff = (((size_t)(n >> 7) * (K1 / 64) + (c8 >> 3)) << 14)
                        + SWZ((n & 127) * 128 + (c8 & 7) * 16);
            *(uint4*)((char*)g_Wf + toff) = *(uint4*)h;
        } else {
            *(uint4*)(g_Wf + (size_t)n * K1 + c) = *(uint4*)h;
        }
    }
}

// Fused middle kernel: pointwise Z (reads linear g_X) + fill Wi
#define PW_BLOCKS 3072
__global__ void mid_pointwise_fillwi(int tiled) {
    if (blockIdx.x < PW_BLOCKS) {
        int idx = blockIdx.x * 256 + threadIdx.x;
        int r = idx >> 7, c8 = idx & 127;
        int f4 = c8 << 2;
        int h = r % HDIM;
        uint4 xu = *(const uint4*)(g_X + (size_t)r * N1 + 2 * f4);
        uint4 ku = *(const uint4*)(g_X + (size_t)(BH + h) * N1 + 2 * f4);
        const __half2* xh = (const __half2*)&xu;
        const __half2* kh = (const __half2*)&ku;
        uint4 zu;
        __half2* zh = (__half2*)&zu;
#pragma unroll
        for (int j = 0; j < 4; j++) {
            float2 X = __half22float2(xh[j]);
            float2 K = __half22float2(kh[j]);
            float alpha = ((f4 + j) == 0) ? (1.0f / 8192.0f) : (2.0f / 8192.0f);
            float Zr = alpha * (X.x * K.x - X.y * K.y);
            float Zi = alpha * (X.x * K.y + X.y * K.x);
            zh[j] = __floats2half2_rn(Zr, -Zi);
        }
        if (tiled) {
            size_t toff = (((size_t)(r >> 7) * (K2 / 64) + (c8 >> 3)) << 14)
                        + SWZ((r & 127) * 128 + (c8 & 7) * 16);
            *(uint4*)((char*)g_Z + toff) = zu;
        } else {
            *(uint4*)(g_Z + (size_t)r * K2 + 2 * f4) = zu;
        }
    } else {
        int idx = (blockIdx.x - PW_BLOCKS) * 256 + threadIdx.x;
        int n = idx >> 7, c8 = idx & 127;
        int c = c8 << 3;
        __half h[8];
#pragma unroll
        for (int j = 0; j < 4; j++) {
            int f = (c >> 1) + j;
            int m = (f * n) & (NFFT - 1);
            float sv, cv;
            __sincosf((float)m * TWO_PI_OVER_N, &sv, &cv);
            h[2 * j]     = __float2half_rn(cv);
            h[2 * j + 1] = __float2half_rn(sv);
        }
        if (tiled) {
            size_t toff = (((size_t)(n >> 7) * (K2 / 64) + (c8 >> 3)) << 14)
                        + SWZ((n & 127) * 128 + (c8 & 7) * 16);
            *(uint4*)((char*)g_Wi + toff) = *(uint4*)h;
        } else {
            *(uint4*)(g_Wi + (size_t)n * K2 + c) = *(uint4*)h;
        }
    }
}

// ====== persistent 4-CTA clusters, occ2, B-multicast across cg2 pairs =========
// 74 clusters x 4 CTAs = 296 CTAs = 2/SM. Cluster = pairs {0,1},{2,3}; a
// supertile = 2 M-tiles (one per pair) x one N=256 tile sharing B.
// A: per-CTA 16KB bulk (tx -> own full). B: 16KB half-panel multicast to
// {0,2} or {1,3}; issuing pair alternates with kt to balance queues.
// Empties are CLUSTER-WIDE (count 2, both issuers commit 0x0F) — R11 fix.
constexpr int STG = 3, BK = 64;
constexpr int BLK16K = 16384;
constexpr int STAGE_B = 2 * BLK16K;                    // A + B = 32 KB
constexpr int SMEM_DYN = 2048 + STG * STAGE_B;         // 100352 B -> occ2

#if HAS_TCGEN05
static constexpr uint64_t SMEM_DESC_BASE_SW128 =
    (uint64_t(2) << 61) | (uint64_t(1) << 46) | (uint64_t(64) << 32) | (uint64_t(1) << 16);
#define MAKE_SMEM_DESC(addr) (SMEM_DESC_BASE_SW128 | ((uint64_t)((addr) >> 4) & 0x3FFF))

#define TCGEN05_ALLOC_CG2(smem_addr, ncols) \
    asm volatile("tcgen05.alloc.cta_group::2.sync.aligned.shared::cta.b32 [%0], %1;" \
                 :: "r"((uint32_t)(smem_addr)), "r"((uint32_t)(ncols)) : "memory")
#define TCGEN05_DEALLOC_CG2(tmem, ncols) \
    asm volatile("tcgen05.dealloc.cta_group::2.sync.aligned.b32 %0, %1;" :: "r"(tmem), "r"((uint32_t)(ncols)))
#define TCGEN05_RELINQ_CG2() \
    asm volatile("tcgen05.relinquish_alloc_permit.cta_group::2.sync.aligned;")
#define TCGEN05_COMMIT_MC_CG2(mbar, mask) \
    asm volatile("tcgen05.commit.cta_group::2.mbarrier::arrive::one.shared::cluster.multicast::cluster.b64 [%0], %1;" \
                 :: "r"((uint32_t)(mbar)), "h"((uint16_t)(mask)) : "memory")
#define TCGEN05_FENCE_AFTER() asm volatile("tcgen05.fence::after_thread_sync;" ::: "memory")
#define TCGEN05_WAIT_LD()     asm volatile("tcgen05.wait::ld.sync.aligned;" ::: "memory")
#define TCGEN05_LD_X32(r, addr) \
    asm volatile("tcgen05.ld.sync.aligned.32x32b.x32.b32 "                         \
        "{%0, %1, %2, %3, %4, %5, %6, %7, %8, %9, %10, %11, %12, %13, %14, %15, "  \
        " %16, %17, %18, %19, %20, %21, %22, %23, %24, %25, %26, %27, %28, %29, %30, %31}, [%32];" \
        : "=r"((r)[0]),  "=r"((r)[1]),  "=r"((r)[2]),  "=r"((r)[3]),               \
          "=r"((r)[4]),  "=r"((r)[5]),  "=r"((r)[6]),  "=r"((r)[7]),               \
          "=r"((r)[8]),  "=r"((r)[9]),  "=r"((r)[10]), "=r"((r)[11]),              \
          "=r"((r)[12]), "=r"((r)[13]), "=r"((r)[14]), "=r"((r)[15]),              \
          "=r"((r)[16]), "=r"((r)[17]), "=r"((r)[18]), "=r"((r)[19]),              \
          "=r"((r)[20]), "=r"((r)[21]), "=r"((r)[22]), "=r"((r)[23]),              \
          "=r"((r)[24]), "=r"((r)[25]), "=r"((r)[26]), "=r"((r)[27]),              \
          "=r"((r)[28]), "=r"((r)[29]), "=r"((r)[30]), "=r"((r)[31])               \
        : "r"(addr))

#define BULK_G2S(dst, src, bytes, mbar) \
    asm volatile("cp.async.bulk.shared::cluster.global.mbarrier::complete_tx::bytes " \
        "[%0], [%1], %2, [%3];" \
        :: "r"((uint32_t)(dst)), "l"(src), "r"((uint32_t)(bytes)), "r"((uint32_t)(mbar)) \
        : "memory")
#define BULK_G2S_MC(dst, src, bytes, mbar, mask) \
    asm volatile("cp.async.bulk.shared::cluster.global.mbarrier::complete_tx::bytes" \
        ".multicast::cluster [%0], [%1], %2, [%3], %4;" \
        :: "r"((uint32_t)(dst)), "l"(src), "r"((uint32_t)(bytes)), "r"((uint32_t)(mbar)), \
           "h"((uint16_t)(mask)) : "memory")

__device__ __forceinline__ void mma_f16_ss_cg2(uint32_t d, uint64_t ad, uint64_t bd,
                                               uint32_t idesc, uint32_t enable) {
    asm volatile(
        "{\n\t.reg .pred p;\n\t"
        "setp.ne.u32 p, %4, 0;\n\t"
        "tcgen05.mma.cta_group::2.kind::f16 [%0], %1, %2, %3, "
        "{%5, %5, %5, %5, %5, %5, %5, %5}, p;\n\t}"
        :: "r"(d), "l"(ad), "l"(bd), "r"(idesc), "r"(enable), "r"(0u)
        : "memory");
}
#endif // HAS_TCGEN05

// WHICH=1: A=g_A(tiled), B=g_Wf(tiled), C=g_X fp16 (M1,N1,K1).
// WHICH=2: A=g_Z(tiled), B=g_Wi(tiled), C=outp fp32 (M2,N2,K2).
template <int KK, int WHICH>
__global__ void __launch_bounds__(256, 2) __cluster_dims__(4, 1, 1)
gemm_blk(float* __restrict__ outp) {
#if HAS_TCGEN05
    extern __shared__ char smem[];
    constexpr int NN = (WHICH == 1) ? N1 : N2;
    constexpr int MM = (WHICH == 1) ? M1 : M2;
    constexpr int KT = KK / BK;
    constexpr int MT = MM / 256;
    constexpr int MSUP = (MT + 1) / 2;
    constexpr int NTn = NN / 256;
    constexpr int NSUPER = MSUP * NTn;
    const char* __restrict__ Atl = (const char*)((WHICH == 1) ? g_A : g_Z);
    const char* __restrict__ Btl = (const char*)((WHICH == 1) ? g_Wf : g_Wi);

    const uint32_t sb = (smem_u32(smem) + 1023u) & ~1023u;
    const uint32_t mb_full  = sb + 8;    // 3 x 8B per CTA
    const uint32_t mb_empty = sb + 40;   // 3 x 8B, CLUSTER-WIDE count 2
    const uint32_t mb_done  = sb + 72;
    const uint32_t mb_free  = sb + 80;
    const uint32_t tb = sb + 1024;

    const int tid = threadIdx.x, wid = tid >> 5, lane = tid & 31;
    const uint32_t rank = cluster_rank();
    const int pair = (int)(rank >> 1), rinp = (int)(rank & 1);
    const int cid = blockIdx.x >> 2;

    if (tid == 0) {
        for (int s = 0; s < STG; s++) {
            MBARRIER_INIT(mb_full + 8 * s, (rinp == 0) ? 2 : 1);  // leader: expect+fwd
            MBARRIER_INIT(mb_empty + 8 * s, 2);                   // both issuers
        }
        MBARRIER_INIT(mb_done, 1);
        MBARRIER_INIT(mb_free, 2);
    }
    if (wid == 4) { TCGEN05_ALLOC_CG2(sb, 256); TCGEN05_RELINQ_CG2(); }
    __syncthreads();
    uint32_t tmem;
    asm volatile("ld.shared.b32 %0, [%1];" : "=r"(tmem) : "r"(sb));
    CLUSTER_SYNC();

    if (tid == 192) {
        // ---------------- producer (warp 6 lane 0, every CTA) -----------------
        const uint16_t bmask = rinp ? 0x0A : 0x05;    // {1,3} : {0,2}
        int s = 0, ph = 0;
        for (int t = cid; t < NSUPER; t += NCL) {
            const int nt = t % NTn, msup = t / NTn;
            int mt = msup * 2 + pair; if (mt >= MT) mt = MT - 1;
            const size_t ablk = (size_t)(mt * 2 + rinp) * KT;
            const size_t bblk = (size_t)(nt * 2 + rinp) * KT;
            for (int kt = 0; kt < KT; kt++) {
                MBARRIER_WAIT_PARITY(mb_empty + 8 * s, ph ^ 1);
                MBARRIER_EXPECT_TX(mb_full + 8 * s, 32768u);
                const uint32_t sA = tb + s * STAGE_B;
                BULK_G2S(sA, Atl + ((ablk + kt) << 14), BLK16K, mb_full + 8 * s);
                if (pair == (kt & 1))                 // alternate B issuer pair
                    BULK_G2S_MC(sA + BLK16K, Btl + ((bblk + kt) << 14), BLK16K,
                                mb_full + 8 * s, bmask);
                if (++s == STG) { s = 0; ph ^= 1; }
            }
        }
    } else if (rinp == 1 && tid == 160) {
        // ---------------- completion forwarder (odd CTAs, warp 5 lane 0) ------
        int s = 0, ph = 0;
        for (int t = cid; t < NSUPER; t += NCL)
            for (int kt = 0; kt < KT; kt++) {
                MBARRIER_WAIT_PARITY(mb_full + 8 * s, ph);
                MBARRIER_ARRIVE_LEADER(mb_full + 8 * s);
                if (++s == STG) { s = 0; ph ^= 1; }
            }
    } else if (rinp == 0 && tid == 224) {
        // ---------------- MMA issuer (pair leaders, warp 7 lane 0) ------------
        const uint32_t idesc = (1u << 4) | (32u << 17) | (16u << 24);  // F32, N=256, M=256
        const uint16_t pmask = pair ? 0x0C : 0x03;
        int s = 0, ph = 0, it = 0;
        for (int t = cid; t < NSUPER; t += NCL, it++) {
            MBARRIER_WAIT_PARITY(mb_free, (it + 1) & 1);
            for (int kt = 0; kt < KT; kt++) {
                MBARRIER_WAIT_PARITY(mb_full + 8 * s, ph);
                const uint64_t ad = MAKE_SMEM_DESC(tb + s * STAGE_B);
                const uint64_t bd = MAKE_SMEM_DESC(tb + s * STAGE_B + BLK16K);
#pragma unroll
                for (int j = 0; j < 4; j++)
                    mma_f16_ss_cg2(tmem, ad + 2 * j, bd + 2 * j, idesc,
                                   (uint32_t)((kt | j) != 0));
                TCGEN05_COMMIT_MC_CG2(mb_empty + 8 * s, 0x0F);   // cluster-wide empty
                if (++s == STG) { s = 0; ph ^= 1; }
            }
            TCGEN05_COMMIT_MC_CG2(mb_done, pmask);
        }
    } else if (tid < 128) {
        // ---------------- epilogue (warps 0-3, every CTA) ---------------------
        int it = 0;
        for (int t = cid; t < NSUPER; t += NCL, it++) {
            MBARRIER_WAIT_PARITY(mb_done, it & 1);
            TCGEN05_FENCE_AFTER();
            const int nt = t % NTn, msup = t / NTn;
            const int mtr = msup * 2 + pair;
            const bool skip = (mtr >= MT);
            const int mt = skip ? MT - 1 : mtr;
            const int grow = mt * 256 + rinp * 128 + wid * 32 + lane;
            if (!skip) {
#pragma unroll
                for (int c0 = 0; c0 < 256; c0 += 32) {
                    uint32_t r[32];
                    TCGEN05_LD_X32(r, tmem + c0);
                    TCGEN05_WAIT_LD();
                    if (WHICH == 1) {
                        uint4 u[2], v[2];
                        __half2* hp = (__half2*)u;
                        __half2* vp = (__half2*)v;
#pragma unroll
                        for (int q = 0; q < 8; q++) {
                            hp[q] = __floats2half2_rn(__uint_as_float(r[2 * q]), __uint_as_float(r[2 * q + 1]));
                            vp[q] = __floats2half2_rn(__uint_as_float(r[16 + 2 * q]), __uint_as_float(r[17 + 2 * q]));
                        }
                        __half* dst = g_X + (size_t)grow * NN + nt * 256 + c0;
                        *(uint4*)(dst)      = u[0];
                        *(uint4*)(dst + 8)  = u[1];
                        *(uint4*)(dst + 16) = v[0];
                        *(uint4*)(dst + 24) = v[1];
                    } else {
                        float* dst = outp + (size_t)grow * NN + nt * 256 + c0;
#pragma unroll
                        for (int q = 0; q < 8; q++) {
                            float4 v4 = make_float4(__uint_as_float(r[4 * q + 0]), __uint_as_float(r[4 * q + 1]),
                                                    __uint_as_float(r[4 * q + 2]), __uint_as_float(r[4 * q + 3]));
                            *(float4*)(dst + 4 * q) = v4;
                        }
                    }
                }
            }
            asm volatile("bar.sync 1, 128;" ::: "memory");
            if (tid == 0) MBARRIER_ARRIVE_LEADER(mb_free);
        }
    }

    __syncthreads();
    if (wid == 4) TCGEN05_DEALLOC_CG2(tmem, 256);
    CLUSTER_SYNC();
#endif // HAS_TCGEN05
}

// ================= HMMA fallback (compiles everywhere; linear layouts) ========
__device__ __forceinline__ void ldsm4(uint32_t& r0, uint32_t& r1, uint32_t& r2, uint32_t& r3, uint32_t a) {
    asm volatile("ldmatrix.sync.aligned.m8n8.x4.shared.b16 {%0,%1,%2,%3}, [%4];\n"
                 : "=r"(r0), "=r"(r1), "=r"(r2), "=r"(r3) : "r"(a));
}
__device__ __forceinline__ void mma16816(float* c, uint32_t a0, uint32_t a1, uint32_t a2, uint32_t a3,
                                         uint32_t b0, uint32_t b1) {
    asm volatile(
        "mma.sync.aligned.m16n8k16.row.col.f32.f16.f16.f32 "
        "{%0,%1,%2,%3}, {%4,%5,%6,%7}, {%8,%9}, {%0,%1,%2,%3};\n"
        : "+f"(c[0]), "+f"(c[1]), "+f"(c[2]), "+f"(c[3])
        : "r"(a0), "r"(a1), "r"(a2), "r"(a3), "r"(b0), "r"(b1));
}

template <int MM, int NN, int KK, int WHICH>
__global__ void __launch_bounds__(256, 2) gemm_hmma(float* __restrict__ outp) {
    const __half* __restrict__ A = (WHICH == 1) ? g_A  : g_Z;
    const __half* __restrict__ B = (WHICH == 1) ? g_Wf : g_Wi;

    constexpr int FBM = 128, FBN = 128, FBK = 32;
    constexpr int LDT = FBK + 8;
    __shared__ __align__(16) __half As[2][FBM * LDT];
    __shared__ __align__(16) __half Bs[2][FBN * LDT];

    const int tid = threadIdx.x, lane = tid & 31, wid = tid >> 5;
    const int wm = wid & 3, wn = wid >> 2;
    const int bm = blockIdx.y * FBM, bn = blockIdx.x * FBN;

    float acc[2][8][4];
#pragma unroll
    for (int i = 0; i < 2; i++)
#pragma unroll
        for (int j = 0; j < 8; j++)
#pragma unroll
            for (int q = 0; q < 4; q++) acc[i][j][q] = 0.f;

    const int trow = tid >> 2, tcol = (tid & 3) << 3;
    auto load_tile = [&](int kt, int buf) {
        const int k0 = kt * FBK;
        const __half* ag = A + (size_t)(bm + trow) * KK + k0 + tcol;
        cp16(smem_u32(&As[buf][trow * LDT + tcol]), ag);
        cp16(smem_u32(&As[buf][(trow + 64) * LDT + tcol]), ag + (size_t)64 * KK);
        const __half* bg = B + (size_t)(bn + trow) * KK + k0 + tcol;
        cp16(smem_u32(&Bs[buf][trow * LDT + tcol]), bg);
        cp16(smem_u32(&Bs[buf][(trow + 64) * LDT + tcol]), bg + (size_t)64 * KK);
        cp_commit();
    };

    load_tile(0, 0);
    constexpr int KT = KK / FBK;
    for (int kt = 0; kt < KT; kt++) {
        const int buf = kt & 1;
        if (kt + 1 < KT) { load_tile(kt + 1, buf ^ 1); cp_wait<1>(); }
        else            { cp_wait<0>(); }
        __syncthreads();
#pragma unroll
        for (int ks = 0; ks < 2; ks++) {
            uint32_t a[2][4], b[4][4];
#pragma unroll
            for (int mt = 0; mt < 2; mt++) {
                int r = wm * 32 + mt * 16 + (lane & 15);
                int c = ks * 16 + ((lane >> 4) << 3);
                ldsm4(a[mt][0], a[mt][1], a[mt][2], a[mt][3], smem_u32(&As[buf][r * LDT + c]));
            }
#pragma unroll
            for (int nt = 0; nt < 4; nt++) {
                int r = wn * 64 + nt * 16 + (lane & 15);
                int c = ks * 16 + ((lane >> 4) << 3);
                ldsm4(b[nt][0], b[nt][1], b[nt][2], b[nt][3], smem_u32(&Bs[buf][r * LDT + c]));
            }
#pragma unroll
            for (int mt = 0; mt < 2; mt++)
#pragma unroll
                for (int nt = 0; nt < 8; nt++)
                    mma16816(acc[mt][nt], a[mt][0], a[mt][1], a[mt][2], a[mt][3],
                             b[nt >> 1][nt & 1], b[nt >> 1][(nt & 1) + 2]);
        }
        __syncthreads();
    }
#pragma unroll
    for (int mt = 0; mt < 2; mt++)
#pragma unroll
        for (int nt = 0; nt < 8; nt++) {
            int row = bm + wm * 32 + mt * 16 + (lane >> 2);
            int col = bn + wn * 64 + nt * 8 + ((lane & 3) << 1);
            if (WHICH == 1) {
                g_X[(size_t)row * NN + col]           = __float2half_rn(acc[mt][nt][0]);
                g_X[(size_t)row * NN + col + 1]       = __float2half_rn(acc[mt][nt][1]);
                g_X[(size_t)(row + 8) * NN + col]     = __float2half_rn(acc[mt][nt][2]);
                g_X[(size_t)(row + 8) * NN + col + 1] = __float2half_rn(acc[mt][nt][3]);
            } else {
                outp[(size_t)row * NN + col]           = acc[mt][nt][0];
                outp[(size_t)row * NN + col + 1]       = acc[mt][nt][1];
                outp[(size_t)(row + 8) * NN + col]     = acc[mt][nt][2];
                outp[(size_t)(row + 8) * NN + col + 1] = acc[mt][nt][3];
            }
        }
}

// ---------------- launch -------------------------------------------------------
extern "C" void kernel_launch(void* const* d_in, const int* in_sizes, int n_in,
                              void* d_out, int out_size) {
    const float* x = (const float*)d_in[0];
    const float* k = (const float*)d_in[1];
    float* out = (float*)d_out;

    cudaFuncAttributes fa{};
    bool use_tc = (cudaFuncGetAttributes(&fa, (const void*)gemm_blk<K1, 1>) == cudaSuccess)
                  && (fa.numRegs >= 40);
    const int tiled = use_tc ? 1 : 0;

    pre_convert_fillwf<<<CV_BLOCKS + (N1 * K1 / 8) / 256, 256>>>(x, k, tiled);

    if (use_tc) {
        cudaFuncSetAttribute((const void*)gemm_blk<K1, 1>,
                             cudaFuncAttributeMaxDynamicSharedMemorySize, SMEM_DYN);
        cudaFuncSetAttribute((const void*)gemm_blk<K2, 2>,
                             cudaFuncAttributeMaxDynamicSharedMemorySize, SMEM_DYN);
        gemm_blk<K1, 1><<<dim3(4 * NCL, 1), 256, SMEM_DYN>>>(nullptr);
        mid_pointwise_fillwi<<<PW_BLOCKS + (N2 * K2 / 8) / 256, 256>>>(tiled);
        gemm_blk<K2, 2><<<dim3(4 * NCL, 1), 256, SMEM_DYN>>>(out);
    } else {
        gemm_hmma<M1, N1, K1, 1><<<dim3(N1 / 128, M1 / 128), 256>>>(nullptr);
        mid_pointwise_fillwi<<<PW_BLOCKS + (N2 * K2 / 8) / 256, 256>>>(tiled);
        gemm_hmma<M2, N2, K2, 2><<<dim3(N2 / 128, M2 / 128), 256>>>(out);
    }
}